// round 3
// baseline (speedup 1.0000x reference)
#include <cuda_runtime.h>
#include <cuda_bf16.h>
#include <math.h>

#define NN 50000
#define EE 1600000
#define FF 64
#define HH 128
#define AA 16
#define NB 49            // ceil(NN/1024)

// ---------------- scratch (device globals; no allocation allowed) ----------
__device__ __align__(16) __nv_bfloat16 g_hb[NN * HH];   // h (current layer, bf16)
__device__ __align__(16) __nv_bfloat16 g_hb2[NN * HH];  // layer-1 output (bf16)
__device__ float g_ssrc[NN];
__device__ float g_sdst[NN];
__device__ int   g_cnt[NN];
__device__ int   g_rowptr[NN + 1];
__device__ int   g_writeptr[NN];
__device__ __align__(16) float4 g_edge[EE];   // {src(int), ea.v1, ea.v2, pad}
__device__ int   g_bsum[64];
__device__ float g_v[4];                      // We1@ae1 (2), We2@ae2 (2)
__device__ float g_pooled[HH];

// ---------------- f32x2 helpers --------------------------------------------
__device__ __forceinline__ unsigned long long f2pk(float x, float y) {
    unsigned long long r;
    asm("mov.b64 %0, {%1,%2};" : "=l"(r) : "f"(x), "f"(y));
    return r;
}
__device__ __forceinline__ void f2fma(unsigned long long& d, unsigned long long a,
                                      unsigned long long b) {
    asm("fma.rn.f32x2 %0, %1, %2, %0;" : "+l"(d) : "l"(a), "l"(b));
}
__device__ __forceinline__ float2 f2unpk(unsigned long long v) {
    float2 r;
    asm("mov.b64 {%0,%1}, %2;" : "=f"(r.x), "=f"(r.y) : "l"(v));
    return r;
}

// ---------------- init ------------------------------------------------------
__global__ void k_zero() {
    int i = blockIdx.x * blockDim.x + threadIdx.x;
    if (i < NN) g_cnt[i] = 0;
    if (i < HH) g_pooled[i] = 0.f;
}

// v = We @ a_e for both layers (ED=2)
__global__ void k_v(const float* __restrict__ We1, const float* __restrict__ ae1,
                    const float* __restrict__ We2, const float* __restrict__ ae2) {
    __shared__ float red[128];
    int t = threadIdx.x;
    float vals[4] = { We1[t] * ae1[t], We1[128 + t] * ae1[t],
                      We2[t] * ae2[t], We2[128 + t] * ae2[t] };
    for (int k = 0; k < 4; k++) {
        red[t] = vals[k];
        __syncthreads();
        for (int off = 64; off > 0; off >>= 1) {
            if (t < off) red[t] += red[t + off];
            __syncthreads();
        }
        if (t == 0) g_v[k] = red[0];
        __syncthreads();
    }
}

// count in-degree per dst
__global__ void k_count(const int* __restrict__ ei) {
    int e = blockIdx.x * blockDim.x + threadIdx.x;
    if (e >= EE) return;
    atomicAdd(&g_cnt[ei[EE + e]], 1);
}

// block-local exclusive scan of g_cnt
__global__ void k_scan1() {
    __shared__ int s[1024];
    int tid = threadIdx.x;
    int i = blockIdx.x * 1024 + tid;
    int c = (i < NN) ? g_cnt[i] : 0;
    s[tid] = c;
    __syncthreads();
    for (int off = 1; off < 1024; off <<= 1) {
        int t = (tid >= off) ? s[tid - off] : 0;
        __syncthreads();
        s[tid] += t;
        __syncthreads();
    }
    if (i < NN) g_rowptr[i] = s[tid] - c;   // exclusive, block-local
    if (tid == 1023) g_bsum[blockIdx.x] = s[1023];
}

// finalize rowptr: each block redundantly scans bsum (49 values), adds offset
__global__ void k_scan23() {
    __shared__ int boff[64];
    if (threadIdx.x == 0) {
        int a = 0;
        for (int b = 0; b < NB; b++) { boff[b] = a; a += g_bsum[b]; }
    }
    __syncthreads();
    int i = blockIdx.x * 1024 + threadIdx.x;
    if (i < NN) {
        int r = g_rowptr[i] + boff[blockIdx.x];
        g_rowptr[i] = r;
        g_writeptr[i] = r;
    }
    if (i == 0) g_rowptr[NN] = EE;
}

// scatter edges into dst-sorted CSR; one 16B packed store per edge
__global__ void k_scatter(const int* __restrict__ ei, const float* __restrict__ ea) {
    int e = blockIdx.x * blockDim.x + threadIdx.x;
    if (e >= EE) return;
    int d = ei[EE + e];
    float e0 = ea[2 * e + 0], e1 = ea[2 * e + 1];
    float v0 = g_v[0], v1 = g_v[1], v2 = g_v[2], v3 = g_v[3];
    int pos = atomicAdd(&g_writeptr[d], 1);
    float4 ed;
    ed.x = __int_as_float(ei[e]);
    ed.y = e0 * v0 + e1 * v1;
    ed.z = e0 * v2 + e1 * v3;
    ed.w = 0.f;
    g_edge[pos] = ed;
}

// ---------------- SGEMM: h = X[N,K] @ W[K,128], f32x2 dual-FMA -------------
// 128x128 block tile, 8x8 per thread, fused attention dots + bf16 store.
template <int K, bool BF16IN>
__global__ __launch_bounds__(256) void k_gemm(const void* __restrict__ Xv,
                                              const float* __restrict__ W,
                                              const float* __restrict__ as_,
                                              const float* __restrict__ ad_,
                                              __nv_bfloat16* __restrict__ Hout) {
    __shared__ float As[16][132];   // [k][row], padded
    __shared__ float Bs[16][128];   // [k][col]
    int tid = threadIdx.x;
    int r0 = blockIdx.x * 128;
    int tx = tid & 15, ty = tid >> 4;
    unsigned long long acc[8][4];
#pragma unroll
    for (int i = 0; i < 8; i++)
#pragma unroll
        for (int j = 0; j < 4; j++) acc[i][j] = 0ull;

    int lr = tid >> 1, kh = tid & 1;          // A loader: row 0..127, k-half
    int wr = tid >> 4, wc = (tid & 15) * 8;   // B loader

    for (int k0 = 0; k0 < K; k0 += 16) {
        float av[8];
        if (r0 + lr < NN) {
            if (BF16IN) {
                uint4 u = *(const uint4*)&((const __nv_bfloat16*)Xv)[(size_t)(r0 + lr) * K + k0 + kh * 8];
                float2 f0 = __bfloat1622float2(*(__nv_bfloat162*)&u.x);
                float2 f1 = __bfloat1622float2(*(__nv_bfloat162*)&u.y);
                float2 f2 = __bfloat1622float2(*(__nv_bfloat162*)&u.z);
                float2 f3 = __bfloat1622float2(*(__nv_bfloat162*)&u.w);
                av[0] = f0.x; av[1] = f0.y; av[2] = f1.x; av[3] = f1.y;
                av[4] = f2.x; av[5] = f2.y; av[6] = f3.x; av[7] = f3.y;
            } else {
                const float* Xf = (const float*)Xv;
                float4 x0 = *(const float4*)&Xf[(size_t)(r0 + lr) * K + k0 + kh * 8];
                float4 x1 = *(const float4*)&Xf[(size_t)(r0 + lr) * K + k0 + kh * 8 + 4];
                av[0] = x0.x; av[1] = x0.y; av[2] = x0.z; av[3] = x0.w;
                av[4] = x1.x; av[5] = x1.y; av[6] = x1.z; av[7] = x1.w;
            }
        } else {
#pragma unroll
            for (int c = 0; c < 8; c++) av[c] = 0.f;
        }
#pragma unroll
        for (int c = 0; c < 8; c++) As[kh * 8 + c][lr] = av[c];

        float4 w0 = *(const float4*)&W[(size_t)(k0 + wr) * HH + wc];
        float4 w1 = *(const float4*)&W[(size_t)(k0 + wr) * HH + wc + 4];
        *(float4*)&Bs[wr][wc] = w0;
        *(float4*)&Bs[wr][wc + 4] = w1;
        __syncthreads();

#pragma unroll
        for (int kk = 0; kk < 16; kk++) {
            float4 a0 = *(const float4*)&As[kk][ty * 8];
            float4 a1 = *(const float4*)&As[kk][ty * 8 + 4];
            float4 b0 = *(const float4*)&Bs[kk][tx * 8];
            float4 b1 = *(const float4*)&Bs[kk][tx * 8 + 4];
            unsigned long long bp[4] = { f2pk(b0.x, b0.y), f2pk(b0.z, b0.w),
                                         f2pk(b1.x, b1.y), f2pk(b1.z, b1.w) };
            float ar[8] = { a0.x, a0.y, a0.z, a0.w, a1.x, a1.y, a1.z, a1.w };
#pragma unroll
            for (int i = 0; i < 8; i++) {
                unsigned long long ap = f2pk(ar[i], ar[i]);
#pragma unroll
                for (int j = 0; j < 4; j++) f2fma(acc[i][j], ap, bp[j]);
            }
        }
        __syncthreads();
    }

    // epilogue: bf16 store + attention dot partials
    float4 as0 = *(const float4*)&as_[tx * 8];
    float4 as1 = *(const float4*)&as_[tx * 8 + 4];
    float4 ad0 = *(const float4*)&ad_[tx * 8];
    float4 ad1 = *(const float4*)&ad_[tx * 8 + 4];
#pragma unroll
    for (int i = 0; i < 8; i++) {
        int row = r0 + ty * 8 + i;
        float2 c0 = f2unpk(acc[i][0]), c1 = f2unpk(acc[i][1]);
        float2 c2 = f2unpk(acc[i][2]), c3 = f2unpk(acc[i][3]);
        float ps = 0.f, pd = 0.f;
        if (row < NN) {
            __nv_bfloat162 p0 = __floats2bfloat162_rn(c0.x, c0.y);
            __nv_bfloat162 p1 = __floats2bfloat162_rn(c1.x, c1.y);
            __nv_bfloat162 p2 = __floats2bfloat162_rn(c2.x, c2.y);
            __nv_bfloat162 p3 = __floats2bfloat162_rn(c3.x, c3.y);
            uint4 pk;
            pk.x = *(unsigned*)&p0; pk.y = *(unsigned*)&p1;
            pk.z = *(unsigned*)&p2; pk.w = *(unsigned*)&p3;
            *(uint4*)&Hout[(size_t)row * HH + tx * 8] = pk;
            ps = c0.x * as0.x + c0.y * as0.y + c1.x * as0.z + c1.y * as0.w
               + c2.x * as1.x + c2.y * as1.y + c3.x * as1.z + c3.y * as1.w;
            pd = c0.x * ad0.x + c0.y * ad0.y + c1.x * ad0.z + c1.y * ad0.w
               + c2.x * ad1.x + c2.y * ad1.y + c3.x * ad1.z + c3.y * ad1.w;
        }
#pragma unroll
        for (int off = 1; off < 16; off <<= 1) {
            ps += __shfl_xor_sync(0xffffffffu, ps, off);
            pd += __shfl_xor_sync(0xffffffffu, pd, off);
        }
        if (tx == 0 && row < NN) { g_ssrc[row] = ps; g_sdst[row] = pd; }
    }
}

__device__ __forceinline__ float lrelu(float x) { return x > 0.f ? x : 0.2f * x; }

__device__ __forceinline__ float4 bf16x4_ld(const __nv_bfloat16* p) {
    uint2 u = *(const uint2*)p;
    float2 f0 = __bfloat1622float2(*(__nv_bfloat162*)&u.x);
    float2 f1 = __bfloat1622float2(*(__nv_bfloat162*)&u.y);
    return make_float4(f0.x, f0.y, f1.x, f1.y);
}

// fused GAT aggregation: one warp/node, online softmax, self-loop merged last.
// LAYER==0: write bf16 to g_hb2. LAYER==1: relu+bias then fused mean-pool.
template <int LAYER>
__global__ __launch_bounds__(256) void k_gat(const float* __restrict__ bias) {
    __shared__ float4 sp[8][32];
    int warp = (blockIdx.x * 256 + threadIdx.x) >> 5;
    int lane = threadIdx.x & 31;
    int wless = (threadIdx.x >> 5);
    int n = warp;                        // NN % 8 == 0 -> always valid
    int rp0 = g_rowptr[n], rp1 = g_rowptr[n + 1];
    float sd = g_sdst[n];

    float m = -3.4e38f;
    float4 acc = make_float4(0.f, 0.f, 0.f, 0.f);
    float denom = 0.f, eacsum = 0.f;

    for (int start = rp0; start < rp1; start += 32) {
        int i = start + lane;
        float lg = -3.4e38f, ec = 0.f;
        int s = 0;
        if (i < rp1) {
            float4 ed = g_edge[i];
            s = __float_as_int(ed.x);
            ec = (LAYER == 0) ? ed.y : ed.z;
            lg = lrelu(g_ssrc[s] + sd + ec);
            eacsum += ec;
        }
        float bm = lg;
#pragma unroll
        for (int off = 16; off; off >>= 1) bm = fmaxf(bm, __shfl_xor_sync(0xffffffffu, bm, off));
        if (bm > m) {
            float sc = __expf(m - bm);
            acc.x *= sc; acc.y *= sc; acc.z *= sc; acc.w *= sc;
            denom *= sc;
            m = bm;
        }
        float p = (i < rp1) ? __expf(lg - m) : 0.f;
        denom += p;
        int cnt = min(32, rp1 - start);
        int j = 0;
        for (; j + 4 <= cnt; j += 4) {
            float p0 = __shfl_sync(0xffffffffu, p, j);
            float p1 = __shfl_sync(0xffffffffu, p, j + 1);
            float p2 = __shfl_sync(0xffffffffu, p, j + 2);
            float p3 = __shfl_sync(0xffffffffu, p, j + 3);
            int s0 = __shfl_sync(0xffffffffu, s, j);
            int s1 = __shfl_sync(0xffffffffu, s, j + 1);
            int s2 = __shfl_sync(0xffffffffu, s, j + 2);
            int s3 = __shfl_sync(0xffffffffu, s, j + 3);
            float4 h0 = bf16x4_ld(&g_hb[(size_t)s0 * HH + lane * 4]);
            float4 h1 = bf16x4_ld(&g_hb[(size_t)s1 * HH + lane * 4]);
            float4 h2 = bf16x4_ld(&g_hb[(size_t)s2 * HH + lane * 4]);
            float4 h3 = bf16x4_ld(&g_hb[(size_t)s3 * HH + lane * 4]);
            acc.x += p0 * h0.x + p1 * h1.x + p2 * h2.x + p3 * h3.x;
            acc.y += p0 * h0.y + p1 * h1.y + p2 * h2.y + p3 * h3.y;
            acc.z += p0 * h0.z + p1 * h1.z + p2 * h2.z + p3 * h3.z;
            acc.w += p0 * h0.w + p1 * h1.w + p2 * h2.w + p3 * h3.w;
        }
        for (; j < cnt; j++) {
            float pj = __shfl_sync(0xffffffffu, p, j);
            int sj = __shfl_sync(0xffffffffu, s, j);
            float4 hv = bf16x4_ld(&g_hb[(size_t)sj * HH + lane * 4]);
            acc.x += pj * hv.x; acc.y += pj * hv.y;
            acc.z += pj * hv.z; acc.w += pj * hv.w;
        }
    }
#pragma unroll
    for (int off = 16; off; off >>= 1) {
        denom  += __shfl_xor_sync(0xffffffffu, denom, off);
        eacsum += __shfl_xor_sync(0xffffffffu, eacsum, off);
    }

    // self-loop (edge_attr = per-dst mean => eac_self = eacsum / cnt)
    float cntf = fmaxf((float)(rp1 - rp0), 1.f);
    float selfl = lrelu(g_ssrc[n] + sd + eacsum / cntf);
    float4 hn = bf16x4_ld(&g_hb[(size_t)n * HH + lane * 4]);
    float mN = fmaxf(m, selfl);
    float sc = __expf(m - mN);
    float ps = __expf(selfl - mN);
    denom = denom * sc + ps;
    acc.x = acc.x * sc + ps * hn.x;
    acc.y = acc.y * sc + ps * hn.y;
    acc.z = acc.z * sc + ps * hn.z;
    acc.w = acc.w * sc + ps * hn.w;

    float inv = 1.f / (denom + 1e-16f);
    float4 bb = *(const float4*)&bias[lane * 4];
    float4 o;
    o.x = fmaxf(acc.x * inv + bb.x, 0.f);
    o.y = fmaxf(acc.y * inv + bb.y, 0.f);
    o.z = fmaxf(acc.z * inv + bb.z, 0.f);
    o.w = fmaxf(acc.w * inv + bb.w, 0.f);

    if (LAYER == 0) {
        __nv_bfloat162 q0 = __floats2bfloat162_rn(o.x, o.y);
        __nv_bfloat162 q1 = __floats2bfloat162_rn(o.z, o.w);
        uint2 pk;
        pk.x = *(unsigned*)&q0; pk.y = *(unsigned*)&q1;
        *(uint2*)&g_hb2[(size_t)n * HH + lane * 4] = pk;
    } else {
        // fused mean-pool: block-level reduce (8 warps) + 128 atomics
        sp[wless][lane] = o;
        __syncthreads();
        if (threadIdx.x < 32) {
            float4 t = sp[0][lane];
#pragma unroll
            for (int w = 1; w < 8; w++) {
                float4 u = sp[w][lane];
                t.x += u.x; t.y += u.y; t.z += u.z; t.w += u.w;
            }
            atomicAdd(&g_pooled[lane * 4 + 0], t.x);
            atomicAdd(&g_pooled[lane * 4 + 1], t.y);
            atomicAdd(&g_pooled[lane * 4 + 2], t.z);
            atomicAdd(&g_pooled[lane * 4 + 3], t.w);
        }
    }
}

// final head: out[a] = tanh(mean_pooled @ Wfc[:,a] + bfc[a])
__global__ void k_head(const float* __restrict__ Wfc, const float* __restrict__ bfc,
                       float* __restrict__ out) {
    int warp = threadIdx.x >> 5;   // 16 warps = AA outputs
    int lane = threadIdx.x & 31;
    float sum = 0.f;
    for (int h = lane; h < HH; h += 32) sum += g_pooled[h] * Wfc[h * AA + warp];
#pragma unroll
    for (int off = 16; off; off >>= 1) sum += __shfl_xor_sync(0xffffffffu, sum, off);
    if (lane == 0) out[warp] = tanhf(sum * (1.0f / NN) + bfc[warp]);
}

// ---------------- launch ----------------------------------------------------
extern "C" void kernel_launch(void* const* d_in, const int* in_sizes, int n_in,
                              void* d_out, int out_size) {
    const float* x      = (const float*)d_in[0];
    const int*   ei     = (const int*)d_in[1];
    const float* ea     = (const float*)d_in[2];
    const float* W1     = (const float*)d_in[3];
    const float* We1    = (const float*)d_in[4];
    const float* asrc1  = (const float*)d_in[5];
    const float* adst1  = (const float*)d_in[6];
    const float* aedge1 = (const float*)d_in[7];
    const float* b1     = (const float*)d_in[8];
    const float* W2     = (const float*)d_in[9];
    const float* We2    = (const float*)d_in[10];
    const float* asrc2  = (const float*)d_in[11];
    const float* adst2  = (const float*)d_in[12];
    const float* aedge2 = (const float*)d_in[13];
    const float* b2     = (const float*)d_in[14];
    const float* Wfc    = (const float*)d_in[15];
    const float* bfc    = (const float*)d_in[16];
    float* out = (float*)d_out;

    void* hb_p = nullptr;  cudaGetSymbolAddress(&hb_p, g_hb);
    void* hb2_p = nullptr; cudaGetSymbolAddress(&hb2_p, g_hb2);
    __nv_bfloat16* hb  = (__nv_bfloat16*)hb_p;
    __nv_bfloat16* hb2 = (__nv_bfloat16*)hb2_p;

    const int EB = (EE + 255) / 256;
    const int NWB = NN / 8;            // 6250 blocks, one warp per node (NN%8==0)

    k_zero<<<(NN + 255) / 256, 256>>>();
    k_v<<<1, 128>>>(We1, aedge1, We2, aedge2);
    k_count<<<EB, 256>>>(ei);
    k_scan1<<<NB, 1024>>>();
    k_scan23<<<NB, 1024>>>();
    k_scatter<<<EB, 256>>>(ei, ea);

    // layer 1
    k_gemm<FF, false><<<(NN + 127) / 128, 256>>>(x, W1, asrc1, adst1, hb);
    k_gat<0><<<NWB, 256>>>(b1);

    // layer 2
    k_gemm<HH, true><<<(NN + 127) / 128, 256>>>(hb2, W2, asrc2, adst2, hb);
    k_gat<1><<<NWB, 256>>>(b2);

    // head
    k_head<<<1, 512>>>(Wfc, bfc, out);
}